// round 1
// baseline (speedup 1.0000x reference)
#include <cuda_runtime.h>

#define IMGW    2048
#define NGRID   256          // 256x256 patches
#define NPATCH  65536
#define NNODES  255
#define KK      64
#define DEPTH   7
#define NLEAF   128
#define NSTRIDE 66           // padded node row stride in shared (floats)

#define SMEM1 (NNODES * NSTRIDE * 4)                    // 67320 B
#define SMEM2 (NPATCH * 2 + 512 * 4 + 512 * 4)          // list + scan + red

__device__ unsigned char g_leaf[NPATCH];
__device__ float g_S[NLEAF * KK];
__device__ float g_cnt[NLEAF];

// ---------------------------------------------------------------------------
// K1: tree descent. One thread = one 8x8 patch held in registers.
// Nodes staged in shared with stride 66 (odd*2 -> distinct banks for
// divergent node rows across lanes).
// ---------------------------------------------------------------------------
__global__ __launch_bounds__(256) void k_descent(const float* __restrict__ image,
                                                 const float* __restrict__ nodes,
                                                 float* __restrict__ out_cur)
{
    extern __shared__ float sh[];   // NNODES * NSTRIDE floats
    const int tid = threadIdx.x;
    for (int i = tid; i < NNODES * KK; i += 256)
        sh[(i >> 6) * NSTRIDE + (i & 63)] = nodes[i];
    __syncthreads();

    const int p  = blockIdx.x * 256 + tid;
    const int pi = p >> 8;
    const int pj = p & 255;
    const float* base = image + (pi * 8) * IMGW + pj * 8;

    float x[64];
#pragma unroll
    for (int r = 0; r < 8; ++r) {
        float4 v0 = *reinterpret_cast<const float4*>(base + r * IMGW);
        float4 v1 = *reinterpret_cast<const float4*>(base + r * IMGW + 4);
        x[r * 8 + 0] = v0.x; x[r * 8 + 1] = v0.y;
        x[r * 8 + 2] = v0.z; x[r * 8 + 3] = v0.w;
        x[r * 8 + 4] = v1.x; x[r * 8 + 5] = v1.y;
        x[r * 8 + 6] = v1.z; x[r * 8 + 7] = v1.w;
    }

    int cur = 0;
#pragma unroll
    for (int lvl = 0; lvl < DEPTH; ++lvl) {
        const int c0 = 2 * cur + 1;
        const float2* r0 = reinterpret_cast<const float2*>(sh + c0 * NSTRIDE);
        const float2* r1 = reinterpret_cast<const float2*>(sh + (c0 + 1) * NSTRIDE);
        float d0 = 0.f, d1 = 0.f;
#pragma unroll
        for (int k = 0; k < 32; ++k) {
            float2 a = r0[k];
            float2 b = r1[k];
            float xa = x[2 * k], xb = x[2 * k + 1];
            float t;
            t = a.x - xa; d0 = fmaf(t, t, d0);
            t = a.y - xb; d0 = fmaf(t, t, d0);
            t = b.x - xa; d1 = fmaf(t, t, d1);
            t = b.y - xb; d1 = fmaf(t, t, d1);
        }
        cur = (d1 < d0) ? (c0 + 1) : c0;   // tie -> left child, matches jnp.where
    }

    g_leaf[p]  = (unsigned char)(cur - 127);
    out_cur[p] = (float)cur;
}

// ---------------------------------------------------------------------------
// K2: per-leaf bucket sums, atomic-free & deterministic.
// One block per leaf. Compact matching patch ids via block scan, then
// re-gather patch pixels from the image (L2-resident) and reduce.
// ---------------------------------------------------------------------------
__global__ __launch_bounds__(512) void k_bucket(const float* __restrict__ image)
{
    extern __shared__ char smem[];
    unsigned short* list = reinterpret_cast<unsigned short*>(smem);          // 65536
    int*   scan = reinterpret_cast<int*>(smem + NPATCH * 2);                 // 512
    float* red  = reinterpret_cast<float*>(smem + NPATCH * 2 + 512 * 4);     // 512

    const int tid  = threadIdx.x;
    const int leaf = blockIdx.x;

    // count matches in this thread's contiguous chunk of 128 patches
    const int base_p = tid * 128;
    int c = 0;
#pragma unroll 8
    for (int i = 0; i < 128; ++i)
        c += (g_leaf[base_p + i] == (unsigned char)leaf);
    scan[tid] = c;
    __syncthreads();

    // Hillis-Steele inclusive scan over 512 thread counts
    for (int off = 1; off < 512; off <<= 1) {
        int v   = scan[tid];
        int add = (tid >= off) ? scan[tid - off] : 0;
        __syncthreads();
        scan[tid] = v + add;
        __syncthreads();
    }
    const int total = scan[511];
    int pos = scan[tid] - c;   // exclusive prefix
    for (int i = 0; i < 128; ++i) {
        int p = base_p + i;
        if (g_leaf[p] == (unsigned char)leaf)
            list[pos++] = (unsigned short)p;
    }
    __syncthreads();

    // 8 patch-slots x 64 elements: thread (slot,k) accumulates a strided
    // slice of the list; order is fixed -> deterministic float sums.
    const int k    = tid & 63;
    const int slot = tid >> 6;
    const int r    = k >> 3;
    const int cc   = k & 7;
    float acc = 0.f;
    for (int i = slot; i < total; i += 8) {
        int p  = list[i];
        int pi = p >> 8;
        int pj = p & 255;
        acc += image[(pi * 8 + r) * IMGW + pj * 8 + cc];
    }
    red[tid] = acc;
    __syncthreads();

    if (tid < 64) {
        float s = 0.f;
#pragma unroll
        for (int sl = 0; sl < 8; ++sl) s += red[sl * 64 + tid];
        g_S[leaf * 64 + tid] = s;
        if (tid == 0) g_cnt[leaf] = (float)total;
    }
}

// ---------------------------------------------------------------------------
// K3: node update. L[l,j] = lrate[common binary prefix of node j+1 and leaf],
// computed with clz — no ancestor table. 255 blocks x 64 threads.
// ---------------------------------------------------------------------------
__global__ __launch_bounds__(64) void k_update(const float* __restrict__ nodes,
                                               float* __restrict__ out_nodes)
{
    const int j = blockIdx.x;     // node row 0..254
    const int k = threadIdx.x;
    if (j == 0) {                 // root is not updated
        out_nodes[k] = nodes[k];
        return;
    }
    const int m  = j + 1;               // 1-indexed node in [2,255]
    const int lv = 31 - __clz(m);       // level of node
    const int a  = m << (7 - lv);       // align to 8-bit leaf domain

    float s1 = 0.f, sc = 0.f;
#pragma unroll 4
    for (int l = 0; l < NLEAF; ++l) {
        int b  = 128 + l;               // 1-indexed leaf
        int xr = a ^ b;
        int mb = xr ? (__clz(xr) - 24) : 8;    // matching leading bits (8-bit)
        int state = min(lv, mb - 1);
        // lrate = 0.3 * 2^(state-7), exact via exponent bits
        float lr = 0.3f * __int_as_float((state + 120) << 23);
        s1 = fmaf(lr, g_S[l * 64 + k], s1);
        sc = fmaf(lr, g_cnt[l], sc);
    }
    const float invP = 1.0f / 65536.0f;
    const float nv = nodes[j * 64 + k];
    out_nodes[j * 64 + k] = nv + s1 * invP - (sc * invP) * nv;
}

// ---------------------------------------------------------------------------
extern "C" void kernel_launch(void* const* d_in, const int* in_sizes, int n_in,
                              void* d_out, int out_size)
{
    const float* image = (const float*)d_in[0];
    const float* nodes = (const float*)d_in[1];
    float* out       = (float*)d_out;
    float* out_nodes = out;                      // 255*64 floats
    float* out_cur   = out + NNODES * KK;        // 65536 floats

    cudaFuncSetAttribute(k_descent, cudaFuncAttributeMaxDynamicSharedMemorySize, SMEM1);
    cudaFuncSetAttribute(k_bucket,  cudaFuncAttributeMaxDynamicSharedMemorySize, SMEM2);

    k_descent<<<256, 256, SMEM1>>>(image, nodes, out_cur);
    k_bucket<<<NLEAF, 512, SMEM2>>>(image);
    k_update<<<NNODES, 64>>>(nodes, out_nodes);
}

// round 2
// speedup vs baseline: 2.6877x; 2.6877x over previous
#include <cuda_runtime.h>

#define IMGW    2048
#define NPATCH  65536
#define NNODES  255
#define NINT    127
#define KK      64
#define DEPTH   7
#define NLEAF   128
#define WSTRIDE 65

__device__ unsigned char g_leaf[NPATCH];
__device__ float g_S[NLEAF * KK];
__device__ float g_cnt[NLEAF];
__device__ float g_W[NINT * KK];
__device__ float g_T[NINT];

// ---------------------------------------------------------------------------
// P0: per internal node i, W[i]=n0-n1 and T[i]=(||n0||^2-||n1||^2)/2.
// Descent decision becomes: go right iff dot(x,W) < T.
// ---------------------------------------------------------------------------
__global__ __launch_bounds__(64) void k_prep(const float* __restrict__ nodes)
{
    const int i = blockIdx.x;          // internal node 0..126
    const int k = threadIdx.x;
    __shared__ float r[64];
    const float n0 = nodes[(2 * i + 1) * KK + k];
    const float n1 = nodes[(2 * i + 2) * KK + k];
    g_W[i * KK + k] = n0 - n1;
    r[k] = n0 * n0 - n1 * n1;
    __syncthreads();
#pragma unroll
    for (int off = 32; off > 0; off >>= 1) {
        if (k < off) r[k] += r[k + off];
        __syncthreads();
    }
    if (k == 0) g_T[i] = 0.5f * r[0];
}

// ---------------------------------------------------------------------------
// K1: tree descent, one thread = one 8x8 patch in registers.
// W staged in shared with stride 65 -> bank = (cur+k)%32, conflict-free
// across divergent rows. 7 x 64 LDS+FMA per thread.
// ---------------------------------------------------------------------------
#define SMEM1 ((NINT * WSTRIDE + NINT) * 4)

__global__ __launch_bounds__(128) void k_descent(const float* __restrict__ image,
                                                 float* __restrict__ out_cur)
{
    extern __shared__ float sh[];            // W swizzled
    float* sT = sh + NINT * WSTRIDE;         // thresholds
    for (int i = threadIdx.x; i < NINT * KK; i += 128)
        sh[(i >> 6) * WSTRIDE + (i & 63)] = g_W[i];
    for (int i = threadIdx.x; i < NINT; i += 128)
        sT[i] = g_T[i];
    __syncthreads();

    const int p  = blockIdx.x * 128 + threadIdx.x;
    const int pi = p >> 8;
    const int pj = p & 255;
    const float* base = image + (pi * 8) * IMGW + pj * 8;

    float x[64];
#pragma unroll
    for (int r = 0; r < 8; ++r) {
        float4 v0 = *reinterpret_cast<const float4*>(base + r * IMGW);
        float4 v1 = *reinterpret_cast<const float4*>(base + r * IMGW + 4);
        x[r * 8 + 0] = v0.x; x[r * 8 + 1] = v0.y;
        x[r * 8 + 2] = v0.z; x[r * 8 + 3] = v0.w;
        x[r * 8 + 4] = v1.x; x[r * 8 + 5] = v1.y;
        x[r * 8 + 6] = v1.z; x[r * 8 + 7] = v1.w;
    }

    int cur = 0;                             // internal node index 0..126
#pragma unroll 1
    for (int lvl = 0; lvl < DEPTH; ++lvl) {
        const float* w = sh + cur * WSTRIDE;
        float a0 = 0.f, a1 = 0.f, a2 = 0.f, a3 = 0.f;
#pragma unroll
        for (int k = 0; k < 64; k += 4) {
            a0 = fmaf(x[k + 0], w[k + 0], a0);
            a1 = fmaf(x[k + 1], w[k + 1], a1);
            a2 = fmaf(x[k + 2], w[k + 2], a2);
            a3 = fmaf(x[k + 3], w[k + 3], a3);
        }
        const float dot = (a0 + a1) + (a2 + a3);
        cur = 2 * cur + 1 + ((dot < sT[cur]) ? 1 : 0);  // right iff dot < T
    }
    // cur is now the 0-indexed leaf node id in [127, 254]
    g_leaf[p]  = (unsigned char)(cur - 127);
    out_cur[p] = (float)cur;
}

// ---------------------------------------------------------------------------
// K2: per-leaf bucket sums, atomic-free & deterministic.
// One block per leaf. Coalesced uint4 scan of g_leaf (kept in regs for
// emission), warp-shuffle prefix scan, float4 gather from L2-resident image.
// ---------------------------------------------------------------------------
#define SMEM2 (NPATCH * 2 + 512 * 16 + 32 * 4 + 16)

__global__ __launch_bounds__(512) void k_bucket(const float* __restrict__ image)
{
    extern __shared__ char smem[];
    unsigned short* list = reinterpret_cast<unsigned short*>(smem);              // 128KB
    float4* red4 = reinterpret_cast<float4*>(smem + NPATCH * 2);                 // 8KB
    int*   wexc  = reinterpret_cast<int*>(smem + NPATCH * 2 + 512 * 16);         // 16 + total

    const int tid  = threadIdx.x;
    const int leaf = blockIdx.x;
    const unsigned lv = (unsigned)leaf * 0x01010101u;
    const uint4* leaf4 = reinterpret_cast<const uint4*>(g_leaf);

    // coalesced count: 8 uint4 per thread, lanes contiguous
    uint4 v[8];
    int c = 0;
#pragma unroll
    for (int j = 0; j < 8; ++j) {
        v[j] = leaf4[j * 512 + tid];
        c += __popc(__vcmpeq4(v[j].x, lv)) + __popc(__vcmpeq4(v[j].y, lv))
           + __popc(__vcmpeq4(v[j].z, lv)) + __popc(__vcmpeq4(v[j].w, lv));
    }
    c >>= 3;

    // warp-shuffle inclusive scan + cross-warp offsets
    const int lane = tid & 31, wid = tid >> 5;
    int incl = c;
#pragma unroll
    for (int off = 1; off < 32; off <<= 1) {
        int n = __shfl_up_sync(0xFFFFFFFFu, incl, off);
        if (lane >= off) incl += n;
    }
    if (lane == 31) wexc[wid] = incl;        // warp totals
    __syncthreads();
    if (tid < 16) {
        int t = wexc[tid];
        int s = t;
#pragma unroll
        for (int off = 1; off < 16; off <<= 1) {
            int n = __shfl_up_sync(0xFFFFu, s, off);
            if (tid >= off) s += n;
        }
        wexc[tid] = s - t;                   // exclusive warp offset
        if (tid == 15) wexc[16] = s;         // grand total
    }
    __syncthreads();
    const int total = wexc[16];
    int pos = wexc[wid] + incl - c;          // global exclusive prefix

    // emission from registers (no re-read of g_leaf)
#pragma unroll
    for (int j = 0; j < 8; ++j) {
#pragma unroll
        for (int word = 0; word < 4; ++word) {
            unsigned wv = (word == 0) ? v[j].x : (word == 1) ? v[j].y
                        : (word == 2) ? v[j].z : v[j].w;
            unsigned cmp = __vcmpeq4(wv, lv);
            if (cmp) {
                const int pb = (j * 512 + tid) * 16 + word * 4;
#pragma unroll
                for (int b = 0; b < 4; ++b)
                    if ((cmp >> (8 * b)) & 1u)
                        list[pos++] = (unsigned short)(pb + b);
            }
        }
    }
    __syncthreads();

    // gather: 32 slots x 16 quads, float4 loads, fixed order -> deterministic
    const int q    = tid & 15;
    const int slot = tid >> 4;
    const int r    = q >> 1;
    const int c4   = (q & 1) * 4;
    float4 acc = make_float4(0.f, 0.f, 0.f, 0.f);
    for (int i = slot; i < total; i += 32) {
        const int p  = list[i];
        const int pi = p >> 8;
        const int pj = p & 255;
        float4 t = *reinterpret_cast<const float4*>(image + (pi * 8 + r) * IMGW + pj * 8 + c4);
        acc.x += t.x; acc.y += t.y; acc.z += t.z; acc.w += t.w;
    }
    red4[tid] = acc;
    __syncthreads();

    if (tid < 16) {
        float4 s = make_float4(0.f, 0.f, 0.f, 0.f);
#pragma unroll
        for (int sl = 0; sl < 32; ++sl) {
            float4 t = red4[sl * 16 + tid];
            s.x += t.x; s.y += t.y; s.z += t.z; s.w += t.w;
        }
        const int k0 = (tid >> 1) * 8 + (tid & 1) * 4;
        *reinterpret_cast<float4*>(g_S + leaf * 64 + k0) = s;
    }
    if (tid == 0) g_cnt[leaf] = (float)total;
}

// ---------------------------------------------------------------------------
// K3: node update via clz common-prefix learning rates (no ancestor table).
// ---------------------------------------------------------------------------
__global__ __launch_bounds__(64) void k_update(const float* __restrict__ nodes,
                                               float* __restrict__ out_nodes)
{
    const int j = blockIdx.x;     // node row 0..254
    const int k = threadIdx.x;
    if (j == 0) {                 // root is not updated
        out_nodes[k] = nodes[k];
        return;
    }
    const int m  = j + 1;               // 1-indexed node in [2,255]
    const int lv = 31 - __clz(m);       // level of node
    const int a  = m << (7 - lv);       // align to 8-bit leaf domain

    float s1 = 0.f, sc = 0.f;
#pragma unroll 4
    for (int l = 0; l < NLEAF; ++l) {
        int b  = 128 + l;               // 1-indexed leaf
        int xr = a ^ b;
        int mb = xr ? (__clz(xr) - 24) : 8;    // matching leading bits (8-bit)
        int state = min(lv, mb - 1);
        // lrate = 0.3 * 2^(state-7), exact via exponent bits
        float lr = 0.3f * __int_as_float((state + 120) << 23);
        s1 = fmaf(lr, g_S[l * 64 + k], s1);
        sc = fmaf(lr, g_cnt[l], sc);
    }
    const float invP = 1.0f / 65536.0f;
    const float nv = nodes[j * 64 + k];
    out_nodes[j * 64 + k] = nv + s1 * invP - (sc * invP) * nv;
}

// ---------------------------------------------------------------------------
extern "C" void kernel_launch(void* const* d_in, const int* in_sizes, int n_in,
                              void* d_out, int out_size)
{
    const float* image = (const float*)d_in[0];
    const float* nodes = (const float*)d_in[1];
    float* out       = (float*)d_out;
    float* out_nodes = out;                      // 255*64 floats
    float* out_cur   = out + NNODES * KK;        // 65536 floats

    cudaFuncSetAttribute(k_bucket, cudaFuncAttributeMaxDynamicSharedMemorySize, SMEM2);

    k_prep<<<NINT, 64>>>(nodes);
    k_descent<<<NPATCH / 128, 128, SMEM1>>>(image, out_cur);
    k_bucket<<<NLEAF, 512, SMEM2>>>(image);
    k_update<<<NNODES, 64>>>(nodes, out_nodes);
}